// round 1
// baseline (speedup 1.0000x reference)
#include <cuda_runtime.h>
#include <math.h>

// Problem constants
#define NHQ   16
#define NKV   8
#define GRP   (NHQ/NKV)     // 2
#define HD    128
#define HID   1024
#define SEQ   2048
#define BATCH 2
#define ROWS  (BATCH*SEQ)   // 4096
#define EPSV  1e-6f

// ---------------- static scratch (no allocs allowed) ----------------
__device__ float g_qraw[(size_t)ROWS * NHQ * HD];           // [B*S, 2048]
__device__ float g_kraw[(size_t)ROWS * NKV * HD];           // [B*S, 1024]
__device__ float g_vraw[(size_t)ROWS * NKV * HD];           // [B*S, 1024]
__device__ float g_q  [(size_t)BATCH * NHQ * SEQ * HD];     // [B,NH,S,HD]
__device__ float g_k  [(size_t)BATCH * NKV * SEQ * HD];     // [B,NKV,S,HD]
__device__ float g_v  [(size_t)BATCH * NKV * SEQ * HD];     // [B,NKV,S,HD]
__device__ float g_att[(size_t)BATCH * NHQ * SEQ * SEQ];    // [B,NH,S,S] 536MB
__device__ float g_ctx[(size_t)BATCH * SEQ * NHQ * HD];     // [B,S,NH,HD]

// ---------------- generic tiled fp32 GEMM ----------------
// C[m,n] = sum_k A[m,k] * B[k,n]   (nn)  or  A[m,k]*Bt[n,k] (nt)
// batched over blockIdx.z with GQA-aware B-head mapping: bhead = (z%nh)/g
constexpr int BM = 64, BN = 64, BK = 16;

__global__ __launch_bounds__(256) void gemm_nn(
    const float* __restrict__ A, const float* __restrict__ B, float* __restrict__ C,
    int M, int N, int K, int lda, int ldb, int ldc,
    long long sAb, long long sAh, long long sBb, long long sBh,
    long long sCb, long long sCh, int nh, int g, int causalK)
{
    int z  = blockIdx.z;
    int zb = z / nh, zh = z - zb * nh;
    A += (long long)zb * sAb + (long long)zh * sAh;
    B += (long long)zb * sBb + (long long)(zh / g) * sBh;
    C += (long long)zb * sCb + (long long)zh * sCh;

    int bx = blockIdx.x, by = blockIdx.y;
    int kEnd = causalK ? min(K, (by + 1) * BM) : K;

    __shared__ float As[BK][BM];
    __shared__ float Bs[BK][BN];

    int tid = threadIdx.x;
    int tx = tid & 15, ty = tid >> 4;
    int ar = tid >> 2, ac = tid & 3;     // A loader: row 0..63, float4 group 0..3
    int br = tid >> 4, bc = tid & 15;    // B loader: row 0..15, float4 group 0..15

    const float* Ap = A + (long long)(by * BM + ar) * lda + ac * 4;
    const float* Bp = B + (long long)br * ldb + bx * BN + bc * 4;

    float acc[4][4] = {};

    for (int k0 = 0; k0 < kEnd; k0 += BK) {
        float4 av = *(const float4*)(Ap + k0);
        float4 bv = *(const float4*)(Bp + (long long)k0 * ldb);
        __syncthreads();
        As[ac * 4 + 0][ar] = av.x;
        As[ac * 4 + 1][ar] = av.y;
        As[ac * 4 + 2][ar] = av.z;
        As[ac * 4 + 3][ar] = av.w;
        *(float4*)(&Bs[br][bc * 4]) = bv;
        __syncthreads();
        #pragma unroll
        for (int kk = 0; kk < BK; kk++) {
            float4 a4 = *(const float4*)(&As[kk][ty * 4]);
            float4 b4 = *(const float4*)(&Bs[kk][tx * 4]);
            float a[4] = {a4.x, a4.y, a4.z, a4.w};
            float b[4] = {b4.x, b4.y, b4.z, b4.w};
            #pragma unroll
            for (int i = 0; i < 4; i++)
                #pragma unroll
                for (int j = 0; j < 4; j++)
                    acc[i][j] += a[i] * b[j];
        }
    }

    float* Cp = C + (long long)(by * BM + ty * 4) * ldc + bx * BN + tx * 4;
    #pragma unroll
    for (int i = 0; i < 4; i++) {
        float4 o = make_float4(acc[i][0], acc[i][1], acc[i][2], acc[i][3]);
        *(float4*)(Cp + (long long)i * ldc) = o;
    }
}

__global__ __launch_bounds__(256) void gemm_nt(
    const float* __restrict__ A, const float* __restrict__ Bt, float* __restrict__ C,
    int M, int N, int K, int lda, int ldb, int ldc,
    long long sAb, long long sAh, long long sBb, long long sBh,
    long long sCb, long long sCh, int nh, int g, int causalSkip)
{
    int bx = blockIdx.x, by = blockIdx.y;
    if (causalSkip && bx * BN > by * BM + (BM - 1)) return;  // strictly-upper tile

    int z  = blockIdx.z;
    int zb = z / nh, zh = z - zb * nh;
    A  += (long long)zb * sAb + (long long)zh * sAh;
    Bt += (long long)zb * sBb + (long long)(zh / g) * sBh;
    C  += (long long)zb * sCb + (long long)zh * sCh;

    __shared__ float As[BK][BM];
    __shared__ float Bs[BK][BN];

    int tid = threadIdx.x;
    int tx = tid & 15, ty = tid >> 4;
    int ar = tid >> 2, ac = tid & 3;
    int nr = tid >> 2, kq = tid & 3;

    const float* Ap = A + (long long)(by * BM + ar) * lda + ac * 4;
    const float* Bp = Bt + (long long)(bx * BN + nr) * ldb + kq * 4;

    float acc[4][4] = {};

    for (int k0 = 0; k0 < K; k0 += BK) {
        float4 av = *(const float4*)(Ap + k0);
        float4 bv = *(const float4*)(Bp + k0);
        __syncthreads();
        As[ac * 4 + 0][ar] = av.x;
        As[ac * 4 + 1][ar] = av.y;
        As[ac * 4 + 2][ar] = av.z;
        As[ac * 4 + 3][ar] = av.w;
        Bs[kq * 4 + 0][nr] = bv.x;
        Bs[kq * 4 + 1][nr] = bv.y;
        Bs[kq * 4 + 2][nr] = bv.z;
        Bs[kq * 4 + 3][nr] = bv.w;
        __syncthreads();
        #pragma unroll
        for (int kk = 0; kk < BK; kk++) {
            float4 a4 = *(const float4*)(&As[kk][ty * 4]);
            float4 b4 = *(const float4*)(&Bs[kk][tx * 4]);
            float a[4] = {a4.x, a4.y, a4.z, a4.w};
            float b[4] = {b4.x, b4.y, b4.z, b4.w};
            #pragma unroll
            for (int i = 0; i < 4; i++)
                #pragma unroll
                for (int j = 0; j < 4; j++)
                    acc[i][j] += a[i] * b[j];
        }
    }

    float* Cp = C + (long long)(by * BM + ty * 4) * ldc + bx * BN + tx * 4;
    #pragma unroll
    for (int i = 0; i < 4; i++) {
        float4 o = make_float4(acc[i][0], acc[i][1], acc[i][2], acc[i][3]);
        *(float4*)(Cp + (long long)i * ldc) = o;
    }
}

// ---------------- RMSNorm + RoPE + transpose ----------------
__device__ __forceinline__ float blockSum128(float v) {
    #pragma unroll
    for (int o = 16; o > 0; o >>= 1) v += __shfl_xor_sync(0xffffffffu, v, o);
    __shared__ float s[4];
    if ((threadIdx.x & 31) == 0) s[threadIdx.x >> 5] = v;
    __syncthreads();
    float r = s[0] + s[1] + s[2] + s[3];
    __syncthreads();
    return r;
}

__global__ __launch_bounds__(HD) void normrope_kernel(
    const float* __restrict__ qraw, const float* __restrict__ kraw,
    const float* __restrict__ vraw,
    const float* __restrict__ qw, const float* __restrict__ kw,
    const int* __restrict__ pos,
    float* __restrict__ q, float* __restrict__ k, float* __restrict__ v)
{
    int row = blockIdx.y;                 // b*SEQ + s
    int h   = blockIdx.x;                 // 0..NHQ+2*NKV-1
    int t   = threadIdx.x;                // 0..127
    int b   = row / SEQ, s = row - b * SEQ;

    if (h >= NHQ + NKV) {                 // V: plain transpose copy
        int kvh = h - NHQ - NKV;
        v[(((long long)b * NKV + kvh) * SEQ + s) * HD + t] =
            vraw[(long long)row * (NKV * HD) + kvh * HD + t];
        return;
    }

    float x; const float* w; float* dst;
    if (h < NHQ) {
        x = qraw[(long long)row * (NHQ * HD) + h * HD + t];
        w = qw;
        dst = q + (((long long)b * NHQ + h) * SEQ + s) * HD + t;
    } else {
        int kvh = h - NHQ;
        x = kraw[(long long)row * (NKV * HD) + kvh * HD + t];
        w = kw;
        dst = k + (((long long)b * NKV + kvh) * SEQ + s) * HD + t;
    }

    // RMSNorm (fp32, matching reference)
    float ms = blockSum128(x * x) * (1.0f / HD);
    float nv = w[t] * (x * rsqrtf(ms + EPSV));

    __shared__ float sh[HD];
    sh[t] = nv;
    __syncthreads();

    // RoPE: emb = concat(freqs, freqs); rotate_half
    int j = t & 63;
    double invf = exp(-(2.0 * j / (double)HD) * log(1.0e6));
    double ang  = (double)pos[s] * invf;
    float c  = (float)cos(ang);
    float sn = (float)sin(ang);
    float partner = (t < 64) ? -sh[t + 64] : sh[t - 64];
    *dst = nv * c + partner * sn;
}

// ---------------- causal softmax (in place, zero-fills j>i) ----------------
__device__ __forceinline__ float blockMax128(float v) {
    #pragma unroll
    for (int o = 16; o > 0; o >>= 1) v = fmaxf(v, __shfl_xor_sync(0xffffffffu, v, o));
    __shared__ float s[4];
    if ((threadIdx.x & 31) == 0) s[threadIdx.x >> 5] = v;
    __syncthreads();
    float r = fmaxf(fmaxf(s[0], s[1]), fmaxf(s[2], s[3]));
    __syncthreads();
    return r;
}

__global__ __launch_bounds__(128) void softmax_causal(float* __restrict__ att, float scale)
{
    int i = blockIdx.x;                       // query index
    long long bh = blockIdx.y;                // b*NHQ + h
    float* row = att + (bh * SEQ + (long long)i) * SEQ;
    int len = i + 1;
    int t = threadIdx.x;

    float mx = -1e30f;
    for (int jj = t; jj < len; jj += 128) mx = fmaxf(mx, row[jj] * scale);
    mx = blockMax128(mx);

    float sum = 0.f;
    for (int jj = t; jj < len; jj += 128) sum += expf(row[jj] * scale - mx);
    sum = blockSum128(sum);
    float inv = 1.0f / sum;

    for (int jj = t; jj < len; jj += 128) row[jj] = expf(row[jj] * scale - mx) * inv;
    for (int jj = t; jj < SEQ; jj += 128) if (jj >= len) row[jj] = 0.0f;
}

// ---------------- launch ----------------
static float* symaddr(const void* sym) {
    void* p = nullptr;
    cudaGetSymbolAddress(&p, sym);
    return (float*)p;
}

extern "C" void kernel_launch(void* const* d_in, const int* in_sizes, int n_in,
                              void* d_out, int out_size)
{
    const float* X   = (const float*)d_in[0];   // [B,S,1024]
    const int*   pos = (const int*)d_in[1];     // [S]
    const float* Wq  = (const float*)d_in[2];   // [1024, 2048]
    const float* Wk  = (const float*)d_in[3];   // [1024, 1024]
    const float* Wv  = (const float*)d_in[4];   // [1024, 1024]
    const float* Wo  = (const float*)d_in[5];   // [2048, 1024]
    const float* qw  = (const float*)d_in[6];   // [128]
    const float* kw  = (const float*)d_in[7];   // [128]
    float* out = (float*)d_out;                 // [B,S,1024]

    float* qraw = symaddr(g_qraw);
    float* kraw = symaddr(g_kraw);
    float* vraw = symaddr(g_vraw);
    float* q    = symaddr(g_q);
    float* k    = symaddr(g_k);
    float* v    = symaddr(g_v);
    float* att  = symaddr(g_att);
    float* ctx  = symaddr(g_ctx);

    const long long SH = (long long)SEQ * HD;          // 262144
    const long long SS = (long long)SEQ * SEQ;         // 4194304

    // 1) QKV projections: [4096,1024] @ W
    gemm_nn<<<dim3((NHQ * HD) / BN, ROWS / BM, 1), 256>>>(
        X, Wq, qraw, ROWS, NHQ * HD, HID, HID, NHQ * HD, NHQ * HD,
        0, 0, 0, 0, 0, 0, 1, 1, 0);
    gemm_nn<<<dim3((NKV * HD) / BN, ROWS / BM, 1), 256>>>(
        X, Wk, kraw, ROWS, NKV * HD, HID, HID, NKV * HD, NKV * HD,
        0, 0, 0, 0, 0, 0, 1, 1, 0);
    gemm_nn<<<dim3((NKV * HD) / BN, ROWS / BM, 1), 256>>>(
        X, Wv, vraw, ROWS, NKV * HD, HID, HID, NKV * HD, NKV * HD,
        0, 0, 0, 0, 0, 0, 1, 1, 0);

    // 2) RMSNorm + RoPE + transpose to [B,H,S,HD]
    normrope_kernel<<<dim3(NHQ + 2 * NKV, ROWS), HD>>>(qraw, kraw, vraw, qw, kw, pos, q, k, v);

    // 3) scores = Q @ K^T per (b,h), causal tiles only
    gemm_nt<<<dim3(SEQ / BN, SEQ / BM, BATCH * NHQ), 256>>>(
        q, k, att, SEQ, SEQ, HD, HD, HD, SEQ,
        (long long)NHQ * SH, SH, (long long)NKV * SH, SH,
        (long long)NHQ * SS, SS, NHQ, GRP, 1);

    // 4) causal softmax with 1/sqrt(HD)
    softmax_causal<<<dim3(SEQ, BATCH * NHQ), 128>>>(att, 0.08838834764831845f);

    // 5) ctx = att @ V  (K-loop causally clamped), write [B,S,NH,HD]
    gemm_nn<<<dim3(HD / BN, SEQ / BM, BATCH * NHQ), 256>>>(
        att, v, ctx, SEQ, HD, SEQ, SEQ, HD, NHQ * HD,
        (long long)NHQ * SS, SS, (long long)NKV * SH, SH,
        (long long)SEQ * NHQ * HD, (long long)HD, NHQ, GRP, 1);

    // 6) out = ctx @ Wo : [4096,2048]@[2048,1024]
    gemm_nn<<<dim3(HID / BN, ROWS / BM, 1), 256>>>(
        ctx, Wo, out, ROWS, HID, NHQ * HD, NHQ * HD, HID, HID,
        0, 0, 0, 0, 0, 0, 1, 1, 0);
}

// round 3
// speedup vs baseline: 1.5633x; 1.5633x over previous
#include <cuda_runtime.h>
#include <cuda_bf16.h>
#include <math.h>

// Problem constants
#define NHQ   16
#define NKV   8
#define GRP   (NHQ/NKV)     // 2
#define HD    128
#define HID   1024
#define SEQ   2048
#define BATCH 2
#define ROWS  (BATCH*SEQ)   // 4096
#define EPSV  1e-6f

// ---------------- static scratch (no allocs allowed) ----------------
__device__ float g_qraw[(size_t)ROWS * NHQ * HD];
__device__ float g_kraw[(size_t)ROWS * NKV * HD];
__device__ float g_vraw[(size_t)ROWS * NKV * HD];
__device__ float g_q  [(size_t)BATCH * NHQ * SEQ * HD];
__device__ float g_k  [(size_t)BATCH * NKV * SEQ * HD];
__device__ float g_v  [(size_t)BATCH * NKV * SEQ * HD];
__device__ float g_att[(size_t)BATCH * NHQ * SEQ * SEQ];    // 536MB
__device__ float g_ctx[(size_t)BATCH * SEQ * NHQ * HD];

// ================= bf16-split tensor-core GEMM =================
// Computes fp32-accurate GEMM via hi/lo bf16 split:
//   C = Ahi*Bhi + Ahi*Blo + Alo*Bhi  (error ~2^-16)
constexpr int BM = 128, BN = 64, BK = 32, NTHR = 256;

__device__ __forceinline__ unsigned su32(const void* p) {
    return (unsigned)__cvta_generic_to_shared(p);
}

__device__ __forceinline__ void ldmx4(unsigned a, unsigned& r0, unsigned& r1,
                                      unsigned& r2, unsigned& r3) {
    asm volatile("ldmatrix.sync.aligned.m8n8.x4.shared.b16 {%0,%1,%2,%3},[%4];\n"
                 : "=r"(r0), "=r"(r1), "=r"(r2), "=r"(r3) : "r"(a));
}
__device__ __forceinline__ void ldmx4t(unsigned a, unsigned& r0, unsigned& r1,
                                       unsigned& r2, unsigned& r3) {
    asm volatile("ldmatrix.sync.aligned.m8n8.x4.trans.shared.b16 {%0,%1,%2,%3},[%4];\n"
                 : "=r"(r0), "=r"(r1), "=r"(r2), "=r"(r3) : "r"(a));
}
__device__ __forceinline__ void mma16816(float* d, const unsigned* a, const unsigned* b) {
    asm volatile(
        "mma.sync.aligned.m16n8k16.row.col.f32.bf16.bf16.f32 "
        "{%0,%1,%2,%3},{%4,%5,%6,%7},{%8,%9},{%0,%1,%2,%3};\n"
        : "+f"(d[0]), "+f"(d[1]), "+f"(d[2]), "+f"(d[3])
        : "r"(a[0]), "r"(a[1]), "r"(a[2]), "r"(a[3]), "r"(b[0]), "r"(b[1]));
}

// 64-byte rows (32 bf16 of k), swizzled to avoid LDSM bank conflicts
__device__ __forceinline__ int offA64(int r, int k) {
    return r * 64 + ((((k >> 3) ^ ((r >> 1) & 3))) << 4) + ((k & 7) << 1);
}
// 128-byte rows (64 bf16 of n), k-row major, classic SW swizzle
__device__ __forceinline__ int offB128(int kr, int n) {
    return kr * 128 + ((((n >> 3) ^ (kr & 7))) << 4) + ((n & 7) << 1);
}

// split one float4 (4 consecutive elements) into bf16 hi/lo and store 8B each
__device__ __forceinline__ void split_store(unsigned char* hiB, unsigned char* loB,
                                            int off, float4 v) {
    __nv_bfloat162 h01 = __floats2bfloat162_rn(v.x, v.y);
    __nv_bfloat162 h23 = __floats2bfloat162_rn(v.z, v.w);
    float2 f01 = __bfloat1622float2(h01);
    float2 f23 = __bfloat1622float2(h23);
    __nv_bfloat162 l01 = __floats2bfloat162_rn(v.x - f01.x, v.y - f01.y);
    __nv_bfloat162 l23 = __floats2bfloat162_rn(v.z - f23.x, v.w - f23.y);
    uint2 hu, lu;
    hu.x = *(unsigned*)&h01; hu.y = *(unsigned*)&h23;
    lu.x = *(unsigned*)&l01; lu.y = *(unsigned*)&l23;
    *(uint2*)(hiB + off) = hu;
    *(uint2*)(loB + off) = lu;
}

// ---------- NT: C[m,n] = sum_k A[m,k] * Bt[n,k] ----------
__global__ __launch_bounds__(NTHR) void mma_gemm_nt(
    const float* __restrict__ A, const float* __restrict__ Bt, float* __restrict__ C,
    int M, int N, int K, int lda, int ldb, int ldc,
    long long sAb, long long sAh, long long sBb, long long sBh,
    long long sCb, long long sCh, int nh, int g, int causalSkip)
{
    int bx = blockIdx.x, by = blockIdx.y;
    if (causalSkip && bx * BN > by * BM + (BM - 1)) return;

    int z = blockIdx.z, zb = z / nh, zh = z - zb * nh;
    A  += (long long)zb * sAb + (long long)zh * sAh;
    Bt += (long long)zb * sBb + (long long)(zh / g) * sBh;
    C  += (long long)zb * sCb + (long long)zh * sCh;

    __shared__ __align__(16) unsigned char sAhi[BM * BK * 2], sAlo[BM * BK * 2];
    __shared__ __align__(16) unsigned char sBhi[BN * BK * 2], sBlo[BN * BK * 2];

    int tid = threadIdx.x, lane = tid & 31, warp = tid >> 5;
    int wm = warp & 3, wn = warp >> 2;

    int lr = tid >> 3;                 // loader row 0..31
    int lk = (tid & 7) << 2;           // loader k 0,4,..28
    const float* Ag = A + (long long)(by * BM + lr) * lda + lk;
    const float* Bg = Bt + (long long)(bx * BN + lr) * ldb + lk;

    float4 a4[4], b4[2];
    float acc[2][4][4];
    #pragma unroll
    for (int i = 0; i < 2; i++)
        #pragma unroll
        for (int j = 0; j < 4; j++)
            #pragma unroll
            for (int t = 0; t < 4; t++) acc[i][j][t] = 0.f;

    int nIter = K / BK;
    #pragma unroll
    for (int i = 0; i < 4; i++) a4[i] = *(const float4*)(Ag + (long long)i * 32 * lda);
    #pragma unroll
    for (int i = 0; i < 2; i++) b4[i] = *(const float4*)(Bg + (long long)i * 32 * ldb);

    int arow = (lane & 7) + ((lane >> 3) & 1) * 8;
    int aksel = (lane >> 4) * 8;
    int bn_l = (lane & 7) + (lane >> 4) * 8;
    int bk_l = ((lane >> 3) & 1) * 8;

    for (int it = 0; it < nIter; ++it) {
        __syncthreads();
        #pragma unroll
        for (int i = 0; i < 4; i++) split_store(sAhi, sAlo, offA64(lr + i * 32, lk), a4[i]);
        #pragma unroll
        for (int i = 0; i < 2; i++) split_store(sBhi, sBlo, offA64(lr + i * 32, lk), b4[i]);
        __syncthreads();
        if (it + 1 < nIter) {
            #pragma unroll
            for (int i = 0; i < 4; i++)
                a4[i] = *(const float4*)(Ag + (it + 1) * BK + (long long)i * 32 * lda);
            #pragma unroll
            for (int i = 0; i < 2; i++)
                b4[i] = *(const float4*)(Bg + (it + 1) * BK + (long long)i * 32 * ldb);
        }
        #pragma unroll
        for (int ks = 0; ks < BK; ks += 16) {
            unsigned ah[2][4], al[2][4], bh[4][2], bl[4][2];
            #pragma unroll
            for (int mt = 0; mt < 2; mt++) {
                int r = wm * 32 + mt * 16 + arow, kk = ks + aksel;
                ldmx4(su32(sAhi + offA64(r, kk)), ah[mt][0], ah[mt][1], ah[mt][2], ah[mt][3]);
                ldmx4(su32(sAlo + offA64(r, kk)), al[mt][0], al[mt][1], al[mt][2], al[mt][3]);
            }
            #pragma unroll
            for (int ng = 0; ng < 2; ng++) {
                int n = wn * 32 + ng * 16 + bn_l, kk = ks + bk_l;
                unsigned r0, r1, r2, r3;
                ldmx4(su32(sBhi + offA64(n, kk)), r0, r1, r2, r3);
                bh[ng * 2][0] = r0; bh[ng * 2][1] = r1; bh[ng * 2 + 1][0] = r2; bh[ng * 2 + 1][1] = r3;
                ldmx4(su32(sBlo + offA64(n, kk)), r0, r1, r2, r3);
                bl[ng * 2][0] = r0; bl[ng * 2][1] = r1; bl[ng * 2 + 1][0] = r2; bl[ng * 2 + 1][1] = r3;
            }
            #pragma unroll
            for (int mt = 0; mt < 2; mt++)
                #pragma unroll
                for (int nt2 = 0; nt2 < 4; nt2++) {
                    mma16816(acc[mt][nt2], ah[mt], bh[nt2]);
                    mma16816(acc[mt][nt2], ah[mt], bl[nt2]);
                    mma16816(acc[mt][nt2], al[mt], bh[nt2]);
                }
        }
    }

    float* Cw = C + (long long)(by * BM + wm * 32) * ldc + bx * BN + wn * 32;
    #pragma unroll
    for (int mt = 0; mt < 2; mt++)
        #pragma unroll
        for (int nt2 = 0; nt2 < 4; nt2++) {
            int r = mt * 16 + (lane >> 2), c = nt2 * 8 + (lane & 3) * 2;
            *(float2*)(Cw + (long long)r * ldc + c) = make_float2(acc[mt][nt2][0], acc[mt][nt2][1]);
            *(float2*)(Cw + (long long)(r + 8) * ldc + c) = make_float2(acc[mt][nt2][2], acc[mt][nt2][3]);
        }
}

// ---------- NN: C[m,n] = sum_k A[m,k] * B[k,n] ----------
__global__ __launch_bounds__(NTHR) void mma_gemm_nn(
    const float* __restrict__ A, const float* __restrict__ B, float* __restrict__ C,
    int M, int N, int K, int lda, int ldb, int ldc,
    long long sAb, long long sAh, long long sBb, long long sBh,
    long long sCb, long long sCh, int nh, int g, int causalK)
{
    int bx = blockIdx.x, by = blockIdx.y;
    int z = blockIdx.z, zb = z / nh, zh = z - zb * nh;
    A += (long long)zb * sAb + (long long)zh * sAh;
    B += (long long)zb * sBb + (long long)(zh / g) * sBh;
    C += (long long)zb * sCb + (long long)zh * sCh;

    __shared__ __align__(16) unsigned char sAhi[BM * BK * 2], sAlo[BM * BK * 2];
    __shared__ __align__(16) unsigned char sBhi[BK * BN * 2], sBlo[BK * BN * 2];

    int tid = threadIdx.x, lane = tid & 31, warp = tid >> 5;
    int wm = warp & 3, wn = warp >> 2;

    int lr = tid >> 3;                 // A loader row
    int lk = (tid & 7) << 2;           // A loader k
    int bkr = tid >> 4;                // B loader k row 0..15
    int bn0 = (tid & 15) << 2;         // B loader n 0..60
    const float* Ag = A + (long long)(by * BM + lr) * lda + lk;
    const float* Bg = B + (long long)bkr * ldb + bx * BN + bn0;

    float4 a4[4], b4[2];
    float acc[2][4][4];
    #pragma unroll
    for (int i = 0; i < 2; i++)
        #pragma unroll
        for (int j = 0; j < 4; j++)
            #pragma unroll
            for (int t = 0; t < 4; t++) acc[i][j][t] = 0.f;

    int kEnd = causalK ? min(K, (by + 1) * BM) : K;
    int nIter = kEnd / BK;

    #pragma unroll
    for (int i = 0; i < 4; i++) a4[i] = *(const float4*)(Ag + (long long)i * 32 * lda);
    #pragma unroll
    for (int i = 0; i < 2; i++) b4[i] = *(const float4*)(Bg + (long long)i * 16 * ldb);

    int arow = (lane & 7) + ((lane >> 3) & 1) * 8;
    int aksel = (lane >> 4) * 8;
    int tk_l = (lane & 7) + ((lane >> 3) & 1) * 8;  // trans-B k within step
    int tn_l = (lane >> 4) * 8;                      // trans-B n offset

    for (int it = 0; it < nIter; ++it) {
        __syncthreads();
        #pragma unroll
        for (int i = 0; i < 4; i++) split_store(sAhi, sAlo, offA64(lr + i * 32, lk), a4[i]);
        #pragma unroll
        for (int i = 0; i < 2; i++) split_store(sBhi, sBlo, offB128(bkr + i * 16, bn0), b4[i]);
        __syncthreads();
        if (it + 1 < nIter) {
            #pragma unroll
            for (int i = 0; i < 4; i++)
                a4[i] = *(const float4*)(Ag + (it + 1) * BK + (long long)i * 32 * lda);
            #pragma unroll
            for (int i = 0; i < 2; i++)
                b4[i] = *(const float4*)(Bg + (long long)((it + 1) * BK + i * 16) * ldb);
        }
        #pragma unroll
        for (int ks = 0; ks < BK; ks += 16) {
            unsigned ah[2][4], al[2][4], bh[4][2], bl[4][2];
            #pragma unroll
            for (int mt = 0; mt < 2; mt++) {
                int r = wm * 32 + mt * 16 + arow, kk = ks + aksel;
                ldmx4(su32(sAhi + offA64(r, kk)), ah[mt][0], ah[mt][1], ah[mt][2], ah[mt][3]);
                ldmx4(su32(sAlo + offA64(r, kk)), al[mt][0], al[mt][1], al[mt][2], al[mt][3]);
            }
            #pragma unroll
            for (int ng = 0; ng < 2; ng++) {
                int kk = ks + tk_l;
                int n = wn * 32 + ng * 16 + tn_l;
                unsigned r0, r1, r2, r3;
                ldmx4t(su32(sBhi + offB128(kk, n)), r0, r1, r2, r3);
                bh[ng * 2][0] = r0; bh[ng * 2][1] = r1; bh[ng * 2 + 1][0] = r2; bh[ng * 2 + 1][1] = r3;
                ldmx4t(su32(sBlo + offB128(kk, n)), r0, r1, r2, r3);
                bl[ng * 2][0] = r0; bl[ng * 2][1] = r1; bl[ng * 2 + 1][0] = r2; bl[ng * 2 + 1][1] = r3;
            }
            #pragma unroll
            for (int mt = 0; mt < 2; mt++)
                #pragma unroll
                for (int nt2 = 0; nt2 < 4; nt2++) {
                    mma16816(acc[mt][nt2], ah[mt], bh[nt2]);
                    mma16816(acc[mt][nt2], ah[mt], bl[nt2]);
                    mma16816(acc[mt][nt2], al[mt], bh[nt2]);
                }
        }
    }

    float* Cw = C + (long long)(by * BM + wm * 32) * ldc + bx * BN + wn * 32;
    #pragma unroll
    for (int mt = 0; mt < 2; mt++)
        #pragma unroll
        for (int nt2 = 0; nt2 < 4; nt2++) {
            int r = mt * 16 + (lane >> 2), c = nt2 * 8 + (lane & 3) * 2;
            *(float2*)(Cw + (long long)r * ldc + c) = make_float2(acc[mt][nt2][0], acc[mt][nt2][1]);
            *(float2*)(Cw + (long long)(r + 8) * ldc + c) = make_float2(acc[mt][nt2][2], acc[mt][nt2][3]);
        }
}

// ---------------- RMSNorm + RoPE + transpose ----------------
__device__ __forceinline__ float blockSum128(float v) {
    #pragma unroll
    for (int o = 16; o > 0; o >>= 1) v += __shfl_xor_sync(0xffffffffu, v, o);
    __shared__ float s[4];
    if ((threadIdx.x & 31) == 0) s[threadIdx.x >> 5] = v;
    __syncthreads();
    float r = s[0] + s[1] + s[2] + s[3];
    __syncthreads();
    return r;
}

__global__ __launch_bounds__(HD) void normrope_kernel(
    const float* __restrict__ qraw, const float* __restrict__ kraw,
    const float* __restrict__ vraw,
    const float* __restrict__ qw, const float* __restrict__ kw,
    const int* __restrict__ pos,
    float* __restrict__ q, float* __restrict__ k, float* __restrict__ v)
{
    int row = blockIdx.y;
    int h   = blockIdx.x;
    int t   = threadIdx.x;
    int b   = row / SEQ, s = row - b * SEQ;

    if (h >= NHQ + NKV) {
        int kvh = h - NHQ - NKV;
        v[(((long long)b * NKV + kvh) * SEQ + s) * HD + t] =
            vraw[(long long)row * (NKV * HD) + kvh * HD + t];
        return;
    }

    float x; const float* w; float* dst;
    if (h < NHQ) {
        x = qraw[(long long)row * (NHQ * HD) + h * HD + t];
        w = qw;
        dst = q + (((long long)b * NHQ + h) * SEQ + s) * HD + t;
    } else {
        int kvh = h - NHQ;
        x = kraw[(long long)row * (NKV * HD) + kvh * HD + t];
        w = kw;
        dst = k + (((long long)b * NKV + kvh) * SEQ + s) * HD + t;
    }

    float ms = blockSum128(x * x) * (1.0f / HD);
    float nv = w[t] * (x * rsqrtf(ms + EPSV));

    __shared__ float sh[HD];
    sh[t] = nv;
    __syncthreads();

    int j = t & 63;
    double invf = exp(-(2.0 * j / (double)HD) * log(1.0e6));
    double ang  = (double)pos[s] * invf;
    float c  = (float)cos(ang);
    float sn = (float)sin(ang);
    float partner = (t < 64) ? -sh[t + 64] : sh[t - 64];
    *dst = nv * c + partner * sn;
}

// ---------------- causal softmax ----------------
__device__ __forceinline__ float blockMax128(float v) {
    #pragma unroll
    for (int o = 16; o > 0; o >>= 1) v = fmaxf(v, __shfl_xor_sync(0xffffffffu, v, o));
    __shared__ float s[4];
    if ((threadIdx.x & 31) == 0) s[threadIdx.x >> 5] = v;
    __syncthreads();
    float r = fmaxf(fmaxf(s[0], s[1]), fmaxf(s[2], s[3]));
    __syncthreads();
    return r;
}

__global__ __launch_bounds__(128) void softmax_causal(float* __restrict__ att, float scale)
{
    int i = blockIdx.x;
    long long bh = blockIdx.y;
    float* row = att + (bh * SEQ + (long long)i) * SEQ;
    int len = i + 1;
    int t = threadIdx.x;

    float mx = -1e30f;
    for (int jj = t; jj < len; jj += 128) mx = fmaxf(mx, row[jj] * scale);
    mx = blockMax128(mx);

    float sum = 0.f;
    for (int jj = t; jj < len; jj += 128) sum += expf(row[jj] * scale - mx);
    sum = blockSum128(sum);
    float inv = 1.0f / sum;

    for (int jj = t; jj < len; jj += 128) row[jj] = expf(row[jj] * scale - mx) * inv;
    for (int jj = t; jj < SEQ; jj += 128) if (jj >= len) row[jj] = 0.0f;
}

// ---------------- launch ----------------
static float* symaddr(const void* sym) {
    void* p = nullptr;
    cudaGetSymbolAddress(&p, sym);
    return (float*)p;
}

extern "C" void kernel_launch(void* const* d_in, const int* in_sizes, int n_in,
                              void* d_out, int out_size)
{
    const float* X   = (const float*)d_in[0];
    const int*   pos = (const int*)d_in[1];
    const float* Wq  = (const float*)d_in[2];
    const float* Wk  = (const float*)d_in[3];
    const float* Wv  = (const float*)d_in[4];
    const float* Wo  = (const float*)d_in[5];
    const float* qw  = (const float*)d_in[6];
    const float* kw  = (const float*)d_in[7];
    float* out = (float*)d_out;

    float* qraw = symaddr(g_qraw);
    float* kraw = symaddr(g_kraw);
    float* vraw = symaddr(g_vraw);
    float* q    = symaddr(g_q);
    float* k    = symaddr(g_k);
    float* v    = symaddr(g_v);
    float* att  = symaddr(g_att);
    float* ctx  = symaddr(g_ctx);

    const long long SH = (long long)SEQ * HD;
    const long long SS = (long long)SEQ * SEQ;

    // 1) QKV projections
    mma_gemm_nn<<<dim3((NHQ * HD) / BN, ROWS / BM, 1), NTHR>>>(
        X, Wq, qraw, ROWS, NHQ * HD, HID, HID, NHQ * HD, NHQ * HD,
        0, 0, 0, 0, 0, 0, 1, 1, 0);
    mma_gemm_nn<<<dim3((NKV * HD) / BN, ROWS / BM, 1), NTHR>>>(
        X, Wk, kraw, ROWS, NKV * HD, HID, HID, NKV * HD, NKV * HD,
        0, 0, 0, 0, 0, 0, 1, 1, 0);
    mma_gemm_nn<<<dim3((NKV * HD) / BN, ROWS / BM, 1), NTHR>>>(
        X, Wv, vraw, ROWS, NKV * HD, HID, HID, NKV * HD, NKV * HD,
        0, 0, 0, 0, 0, 0, 1, 1, 0);

    // 2) RMSNorm + RoPE + transpose
    normrope_kernel<<<dim3(NHQ + 2 * NKV, ROWS), HD>>>(qraw, kraw, vraw, qw, kw, pos, q, k, v);

    // 3) scores = Q @ K^T, causal tiles only
    mma_gemm_nt<<<dim3(SEQ / BN, SEQ / BM, BATCH * NHQ), NTHR>>>(
        q, k, att, SEQ, SEQ, HD, HD, HD, SEQ,
        (long long)NHQ * SH, SH, (long long)NKV * SH, SH,
        (long long)NHQ * SS, SS, NHQ, GRP, 1);

    // 4) causal softmax
    softmax_causal<<<dim3(SEQ, BATCH * NHQ), 128>>>(att, 0.08838834764831845f);

    // 5) ctx = att @ V (K causally clamped)
    mma_gemm_nn<<<dim3(HD / BN, SEQ / BM, BATCH * NHQ), NTHR>>>(
        att, v, ctx, SEQ, HD, SEQ, SEQ, HD, NHQ * HD,
        (long long)NHQ * SS, SS, (long long)NKV * SH, SH,
        (long long)SEQ * NHQ * HD, (long long)HD, NHQ, GRP, 1);

    // 6) out = ctx @ Wo
    mma_gemm_nn<<<dim3(HID / BN, ROWS / BM, 1), NTHR>>>(
        ctx, Wo, out, ROWS, HID, NHQ * HD, NHQ * HD, HID, HID,
        0, 0, 0, 0, 0, 0, 1, 1, 0);
}

// round 5
// speedup vs baseline: 1.6777x; 1.0731x over previous
#include <cuda_runtime.h>
#include <cuda_bf16.h>
#include <math.h>

#define NHQ   16
#define NKV   8
#define HD    128
#define HID   1024
#define SEQ   2048
#define BATCH 2
#define ROWS  (BATCH*SEQ)   // 4096
#define EPSV  1e-6f

typedef __nv_bfloat16 bf16;

// log2(e)/sqrt(128): folded into Q so scores are in log2 domain
#define QSCALE 0.12753123810100868f

// ---------------- static scratch ----------------
__device__ __align__(256) float g_qraw[(size_t)ROWS * NHQ * HD];
__device__ __align__(256) float g_kraw[(size_t)ROWS * NKV * HD];
__device__ __align__(256) float g_vraw[(size_t)ROWS * NKV * HD];

__device__ __align__(256) bf16 g_xhi[(size_t)ROWS * HID];
__device__ __align__(256) bf16 g_xlo[(size_t)ROWS * HID];
__device__ __align__(256) bf16 g_wqhi[(size_t)HID * NHQ * HD];
__device__ __align__(256) bf16 g_wqlo[(size_t)HID * NHQ * HD];
__device__ __align__(256) bf16 g_wkhi[(size_t)HID * NKV * HD];
__device__ __align__(256) bf16 g_wklo[(size_t)HID * NKV * HD];
__device__ __align__(256) bf16 g_wvhi[(size_t)HID * NKV * HD];
__device__ __align__(256) bf16 g_wvlo[(size_t)HID * NKV * HD];
__device__ __align__(256) bf16 g_wohi[(size_t)NHQ * HD * HID];
__device__ __align__(256) bf16 g_wolo[(size_t)NHQ * HD * HID];

__device__ __align__(256) bf16 g_qhi[(size_t)BATCH * NHQ * SEQ * HD];
__device__ __align__(256) bf16 g_qlo[(size_t)BATCH * NHQ * SEQ * HD];
__device__ __align__(256) bf16 g_khi[(size_t)BATCH * NKV * SEQ * HD];
__device__ __align__(256) bf16 g_klo[(size_t)BATCH * NKV * SEQ * HD];
__device__ __align__(256) bf16 g_vhi[(size_t)BATCH * NKV * SEQ * HD];
__device__ __align__(256) bf16 g_vlo[(size_t)BATCH * NKV * SEQ * HD];

__device__ __align__(256) bf16 g_chi[(size_t)ROWS * NHQ * HD];
__device__ __align__(256) bf16 g_clo[(size_t)ROWS * NHQ * HD];

// ---------------- PTX helpers ----------------
__device__ __forceinline__ unsigned su32(const void* p) {
    return (unsigned)__cvta_generic_to_shared(p);
}
__device__ __forceinline__ void cp16(unsigned d, const void* s) {
    asm volatile("cp.async.ca.shared.global [%0],[%1],16;\n" :: "r"(d), "l"(s));
}
__device__ __forceinline__ void cpcommit() { asm volatile("cp.async.commit_group;\n"); }
#define CP_WAIT1() asm volatile("cp.async.wait_group 1;\n")
#define CP_WAIT0() asm volatile("cp.async.wait_group 0;\n")

__device__ __forceinline__ void ldmx4(unsigned a, unsigned& r0, unsigned& r1,
                                      unsigned& r2, unsigned& r3) {
    asm volatile("ldmatrix.sync.aligned.m8n8.x4.shared.b16 {%0,%1,%2,%3},[%4];\n"
                 : "=r"(r0), "=r"(r1), "=r"(r2), "=r"(r3) : "r"(a));
}
__device__ __forceinline__ void ldmx4t(unsigned a, unsigned& r0, unsigned& r1,
                                       unsigned& r2, unsigned& r3) {
    asm volatile("ldmatrix.sync.aligned.m8n8.x4.trans.shared.b16 {%0,%1,%2,%3},[%4];\n"
                 : "=r"(r0), "=r"(r1), "=r"(r2), "=r"(r3) : "r"(a));
}
__device__ __forceinline__ void mma16816(float* d, const unsigned* a, const unsigned* b) {
    asm volatile(
        "mma.sync.aligned.m16n8k16.row.col.f32.bf16.bf16.f32 "
        "{%0,%1,%2,%3},{%4,%5,%6,%7},{%8,%9},{%0,%1,%2,%3};\n"
        : "+f"(d[0]), "+f"(d[1]), "+f"(d[2]), "+f"(d[3])
        : "r"(a[0]), "r"(a[1]), "r"(a[2]), "r"(a[3]), "r"(b[0]), "r"(b[1]));
}
__device__ __forceinline__ float ex2(float x) {
    float r;
    asm("ex2.approx.ftz.f32 %0, %1;" : "=f"(r) : "f"(x));
    return r;
}
__device__ __forceinline__ void split2(float x, float y, unsigned& hi, unsigned& lo) {
    __nv_bfloat162 h = __floats2bfloat162_rn(x, y);
    float2 hf = __bfloat1622float2(h);
    __nv_bfloat162 l = __floats2bfloat162_rn(x - hf.x, y - hf.y);
    hi = *(unsigned*)&h;
    lo = *(unsigned*)&l;
}

// swizzled smem offsets (bytes). 64B rows / 256B rows, conflict-free for ldmatrix.
__device__ __forceinline__ int offA64(int r, int k) {
    return r * 64 + ((((k >> 3) ^ ((r >> 1) & 3))) << 4) + ((k & 7) << 1);
}
__device__ __forceinline__ int off256(int r, int n) {
    return r * 256 + ((((n >> 3) ^ (r & 7))) << 4) + ((n & 7) << 1);
}

// ---------------- elementwise fp32 -> bf16 hi/lo split ----------------
__global__ __launch_bounds__(256) void split_kernel(
    const float* __restrict__ x, bf16* __restrict__ hi, bf16* __restrict__ lo, int n)
{
    for (int i = blockIdx.x * 256 + threadIdx.x; i < n; i += gridDim.x * 256) {
        float v = x[i];
        bf16 h = __float2bfloat16(v);
        hi[i] = h;
        lo[i] = __float2bfloat16(v - __bfloat162float(h));
    }
}

// ================= double-buffered bf16-split GEMM (NN) =================
// C[m,n] = sum_k A[m,k]*B[k,n], A/B pre-split hi/lo bf16, fp32 out.
// C = Ahi*Bhi + Ahi*Blo + Alo*Bhi
constexpr int GBM = 128, GBN = 128, GBK = 32;
// smem: stage s at s*32768: Ahi 0, Alo 8192, Bhi 16384, Blo 24576. total 64KB.

__global__ __launch_bounds__(256) void gemm_split(
    const bf16* __restrict__ Ahi, const bf16* __restrict__ Alo,
    const bf16* __restrict__ Bhi, const bf16* __restrict__ Blo,
    float* __restrict__ C, int M, int N, int K)
{
    extern __shared__ char sm[];
    int tid = threadIdx.x, lane = tid & 31, warp = tid >> 5;
    int bx = blockIdx.x, by = blockIdx.y;
    int wm = warp >> 2, wn = warp & 3;

    float acc[4][4][4];
    #pragma unroll
    for (int a = 0; a < 4; a++)
        #pragma unroll
        for (int b = 0; b < 4; b++)
            #pragma unroll
            for (int c = 0; c < 4; c++) acc[a][b][c] = 0.f;

    int nIter = K / GBK;

    // loader indices
    int ar = tid >> 2, ag = (tid & 3) << 3;        // A: row, k-group(8 elems)
    int bkr = tid >> 4, bg = (tid & 15) << 3;      // B: k-row, n-group

    // issue stage st for k-offset k0
    auto issue = [&](int st, int k0) {
        char* base = sm + st * 32768;
        #pragma unroll
        for (int p = 0; p < 2; p++) {
            int r = ar + p * 64;
            int so = offA64(r, ag);
            size_t go = (size_t)(by * GBM + r) * K + k0 + ag;
            cp16(su32(base + so), Ahi + go);
            cp16(su32(base + 8192 + so), Alo + go);
        }
        #pragma unroll
        for (int p = 0; p < 2; p++) {
            int kr = bkr + p * 16;
            int so = off256(kr, bg);
            size_t go = (size_t)(k0 + kr) * N + bx * GBN + bg;
            cp16(su32(base + 16384 + so), Bhi + go);
            cp16(su32(base + 24576 + so), Blo + go);
        }
    };

    issue(0, 0);
    cpcommit();

    int arow = (lane & 7) + ((lane >> 3) & 1) * 8;
    int aksel = (lane >> 4) * 8;
    int tk = (lane & 7) + ((lane >> 3) & 1) * 8;
    int tn = (lane >> 4) * 8;

    for (int it = 0; it < nIter; ++it) {
        if (it + 1 < nIter) {
            issue((it + 1) & 1, (it + 1) * GBK);
            cpcommit();
            CP_WAIT1();
        } else {
            CP_WAIT0();
        }
        __syncthreads();
        char* base = sm + (it & 1) * 32768;

        #pragma unroll
        for (int ks = 0; ks < GBK; ks += 16) {
            unsigned ah[4][4], al[4][4], bh[4][2], bl[4][2];
            #pragma unroll
            for (int mt = 0; mt < 4; mt++) {
                int so = offA64(wm * 64 + mt * 16 + arow, ks + aksel);
                ldmx4(su32(base + so), ah[mt][0], ah[mt][1], ah[mt][2], ah[mt][3]);
                ldmx4(su32(base + 8192 + so), al[mt][0], al[mt][1], al[mt][2], al[mt][3]);
            }
            #pragma unroll
            for (int ng = 0; ng < 2; ng++) {
                int so = off256(ks + tk, wn * 32 + ng * 16 + tn);
                unsigned r0, r1, r2, r3;
                ldmx4t(su32(base + 16384 + so), r0, r1, r2, r3);
                bh[2 * ng][0] = r0; bh[2 * ng][1] = r1;
                bh[2 * ng + 1][0] = r2; bh[2 * ng + 1][1] = r3;
                ldmx4t(su32(base + 24576 + so), r0, r1, r2, r3);
                bl[2 * ng][0] = r0; bl[2 * ng][1] = r1;
                bl[2 * ng + 1][0] = r2; bl[2 * ng + 1][1] = r3;
            }
            #pragma unroll
            for (int mt = 0; mt < 4; mt++)
                #pragma unroll
                for (int nf = 0; nf < 4; nf++) {
                    mma16816(acc[mt][nf], ah[mt], bh[nf]);
                    mma16816(acc[mt][nf], ah[mt], bl[nf]);
                    mma16816(acc[mt][nf], al[mt], bh[nf]);
                }
        }
        __syncthreads();
    }

    #pragma unroll
    for (int mt = 0; mt < 4; mt++)
        #pragma unroll
        for (int nf = 0; nf < 4; nf++) {
            int r = by * GBM + wm * 64 + mt * 16 + (lane >> 2);
            int c = bx * GBN + wn * 32 + nf * 8 + (lane & 3) * 2;
            *(float2*)(C + (size_t)r * N + c) = make_float2(acc[mt][nf][0], acc[mt][nf][1]);
            *(float2*)(C + (size_t)(r + 8) * N + c) = make_float2(acc[mt][nf][2], acc[mt][nf][3]);
        }
}

// ================= fused flash attention =================
// grid (16, BATCH*NHQ). CTA: 128 q-rows, loop 64-kv tiles (double buffered).
// smem: Qhi 0 (32KB), Qlo 32768; stage s at 65536+s*65536:
//       Khi +0, Klo +16384, Vhi +32768, Vlo +49152. total 192KB.
__global__ __launch_bounds__(256) void flash_kernel(
    const bf16* __restrict__ qhi, const bf16* __restrict__ qlo,
    const bf16* __restrict__ khi, const bf16* __restrict__ klo,
    const bf16* __restrict__ vhi, const bf16* __restrict__ vlo,
    bf16* __restrict__ chi, bf16* __restrict__ clo)
{
    extern __shared__ char sm[];
    int tid = threadIdx.x, lane = tid & 31, wid = tid >> 5;
    int qt = (gridDim.x - 1) - blockIdx.x;   // big tiles first
    int bh = blockIdx.y;
    int b = bh >> 4, h = bh & 15, kvh = h >> 1;

    size_t qbase = ((size_t)(b * NHQ + h) * SEQ + (size_t)qt * 128) * HD;
    size_t kvbase = (size_t)(b * NKV + kvh) * SEQ * HD;

    // load Q (hi+lo)
    #pragma unroll
    for (int p = 0; p < 8; p++) {
        int idx = tid + p * 256;
        int r = idx >> 4, g = (idx & 15) << 3;
        int so = off256(r, g);
        size_t go = qbase + (size_t)r * HD + g;
        cp16(su32(sm + so), qhi + go);
        cp16(su32(sm + 32768 + so), qlo + go);
    }
    cpcommit();

    auto issueKV = [&](int st, int kt) {
        char* base = sm + 65536 + st * 65536;
        size_t kb = kvbase + (size_t)kt * 64 * HD;
        #pragma unroll
        for (int p = 0; p < 4; p++) {
            int idx = tid + p * 256;
            int r = idx >> 4, g = (idx & 15) << 3;
            int so = off256(r, g);
            size_t go = kb + (size_t)r * HD + g;
            cp16(su32(base + so), khi + go);
            cp16(su32(base + 16384 + so), klo + go);
            cp16(su32(base + 32768 + so), vhi + go);
            cp16(su32(base + 49152 + so), vlo + go);
        }
    };

    int nT = 2 * qt + 2;
    issueKV(0, 0);
    cpcommit();

    float oacc[16][4];
    #pragma unroll
    for (int f = 0; f < 16; f++)
        #pragma unroll
        for (int c = 0; c < 4; c++) oacc[f][c] = 0.f;
    float m0 = -1e30f, m1 = -1e30f, l0 = 0.f, l1 = 0.f;

    int arow = (lane & 7) + ((lane >> 3) & 1) * 8;
    int aksel = (lane >> 4) * 8;
    int bn = (lane & 7) + (lane >> 4) * 8;
    int bk = ((lane >> 3) & 1) * 8;
    int tk = (lane & 7) + ((lane >> 3) & 1) * 8;
    int tn = (lane >> 4) * 8;
    int r0g = qt * 128 + wid * 16 + (lane >> 2);

    for (int kt = 0; kt < nT; ++kt) {
        if (kt + 1 < nT) {
            issueKV((kt + 1) & 1, kt + 1);
            cpcommit();
            CP_WAIT1();
        } else {
            CP_WAIT0();
        }
        __syncthreads();
        char* kbase = sm + 65536 + (kt & 1) * 65536;
        char* vbase = kbase + 32768;

        // ---- S = Q*K^T (16 x 64 per warp), log2 domain ----
        float sacc[8][4];
        #pragma unroll
        for (int f = 0; f < 8; f++)
            #pragma unroll
            for (int c = 0; c < 4; c++) sacc[f][c] = 0.f;

        #pragma unroll
        for (int ks = 0; ks < HD; ks += 16) {
            unsigned qh[4], ql[4];
            int qo = off256(wid * 16 + arow, ks + aksel);
            ldmx4(su32(sm + qo), qh[0], qh[1], qh[2], qh[3]);
            ldmx4(su32(sm + 32768 + qo), ql[0], ql[1], ql[2], ql[3]);
            #pragma unroll
            for (int ng = 0; ng < 4; ng++) {
                int so = off256(ng * 16 + bn, ks + bk);
                unsigned r0, r1, r2, r3;
                unsigned kh0[2], kh1[2], kl0[2], kl1[2];
                ldmx4(su32(kbase + so), r0, r1, r2, r3);
                kh0[0] = r0; kh0[1] = r1; kh1[0] = r2; kh1[1] = r3;
                ldmx4(su32(kbase + 16384 + so), r0, r1, r2, r3);
                kl0[0] = r0; kl0[1] = r1; kl1[0] = r2; kl1[1] = r3;
                mma16816(sacc[2 * ng], qh, kh0);
                mma16816(sacc[2 * ng], qh, kl0);
                mma16816(sacc[2 * ng], ql, kh0);
                mma16816(sacc[2 * ng + 1], qh, kh1);
                mma16816(sacc[2 * ng + 1], qh, kl1);
                mma16816(sacc[2 * ng + 1], ql, kh1);
            }
        }

        // ---- causal mask (only tiles overlapping diagonal) ----
        if (kt >= 2 * qt) {
            #pragma unroll
            for (int nf = 0; nf < 8; nf++) {
                int col = kt * 64 + nf * 8 + (lane & 3) * 2;
                if (col > r0g)     sacc[nf][0] = -1e30f;
                if (col + 1 > r0g) sacc[nf][1] = -1e30f;
                if (col > r0g + 8)     sacc[nf][2] = -1e30f;
                if (col + 1 > r0g + 8) sacc[nf][3] = -1e30f;
            }
        }

        // ---- online softmax ----
        float tm0 = -1e30f, tm1 = -1e30f;
        #pragma unroll
        for (int nf = 0; nf < 8; nf++) {
            tm0 = fmaxf(tm0, fmaxf(sacc[nf][0], sacc[nf][1]));
            tm1 = fmaxf(tm1, fmaxf(sacc[nf][2], sacc[nf][3]));
        }
        tm0 = fmaxf(tm0, __shfl_xor_sync(0xffffffffu, tm0, 1));
        tm0 = fmaxf(tm0, __shfl_xor_sync(0xffffffffu, tm0, 2));
        tm1 = fmaxf(tm1, __shfl_xor_sync(0xffffffffu, tm1, 1));
        tm1 = fmaxf(tm1, __shfl_xor_sync(0xffffffffu, tm1, 2));
        float mn0 = fmaxf(m0, tm0), mn1 = fmaxf(m1, tm1);
        float al0 = ex2(m0 - mn0), al1 = ex2(m1 - mn1);
        m0 = mn0; m1 = mn1;

        float ps0 = 0.f, ps1 = 0.f;
        #pragma unroll
        for (int nf = 0; nf < 8; nf++) {
            sacc[nf][0] = ex2(sacc[nf][0] - mn0);
            sacc[nf][1] = ex2(sacc[nf][1] - mn0);
            sacc[nf][2] = ex2(sacc[nf][2] - mn1);
            sacc[nf][3] = ex2(sacc[nf][3] - mn1);
            ps0 += sacc[nf][0] + sacc[nf][1];
            ps1 += sacc[nf][2] + sacc[nf][3];
        }
        l0 = l0 * al0 + ps0;
        l1 = l1 * al1 + ps1;
        #pragma unroll
        for (int f = 0; f < 16; f++) {
            oacc[f][0] *= al0; oacc[f][1] *= al0;
            oacc[f][2] *= al1; oacc[f][3] *= al1;
        }

        // ---- P -> bf16 hi/lo A-fragments (k = kv dim, 4 k16 blocks) ----
        unsigned pah[4][4], pal[4][4];
        #pragma unroll
        for (int j = 0; j < 4; j++) {
            split2(sacc[2 * j][0], sacc[2 * j][1], pah[j][0], pal[j][0]);
            split2(sacc[2 * j][2], sacc[2 * j][3], pah[j][1], pal[j][1]);
            split2(sacc[2 * j + 1][0], sacc[2 * j + 1][1], pah[j][2], pal[j][2]);
            split2(sacc[2 * j + 1][2], sacc[2 * j + 1][3], pah[j][3], pal[j][3]);
        }

        // ---- O += P*V ----
        #pragma unroll
        for (int j = 0; j < 4; j++) {
            #pragma unroll
            for (int ng2 = 0; ng2 < 8; ng2++) {
                int so = off256(j * 16 + tk, ng2 * 16 + tn);
                unsigned r0, r1, r2, r3, s0, s1, s2, s3;
                ldmx4t(su32(vbase + so), r0, r1, r2, r3);
                ldmx4t(su32(vbase + 16384 + so), s0, s1, s2, s3);
                unsigned vh0[2] = {r0, r1}, vh1[2] = {r2, r3};
                unsigned vl0[2] = {s0, s1}, vl1[2] = {s2, s3};
                mma16816(oacc[2 * ng2], pah[j], vh0);
                mma16816(oacc[2 * ng2], pal[j], vh0);
                mma16816(oacc[2 * ng2], pah[j], vl0);
                mma16816(oacc[2 * ng2 + 1], pah[j], vh1);
                mma16816(oacc[2 * ng2 + 1], pal[j], vh1);
                mma16816(oacc[2 * ng2 + 1], pah[j], vl1);
            }
        }
        __syncthreads();
    }

    // ---- finalize: O /= l, write ctx hi/lo [ROWS, 2048] ----
    l0 += __shfl_xor_sync(0xffffffffu, l0, 1);
    l0 += __shfl_xor_sync(0xffffffffu, l0, 2);
    l1 += __shfl_xor_sync(0xffffffffu, l1, 1);
    l1 += __shfl_xor_sync(0xffffffffu, l1, 2);
    float i0 = 1.f / l0, i1 = 1.f / l1;

    size_t row0 = (size_t)b * SEQ + qt * 128 + wid * 16 + (lane >> 2);
    #pragma unroll
    for (int nf = 0; nf < 16; nf++) {
        int col = h * HD + nf * 8 + (lane & 3) * 2;
        unsigned hi, lo;
        split2(oacc[nf][0] * i0, oacc[nf][1] * i0, hi, lo);
        *(unsigned*)(chi + row0 * (NHQ * HD) + col) = hi;
        *(unsigned*)(clo + row0 * (NHQ * HD) + col) = lo;
        split2(oacc[nf][2] * i1, oacc[nf][3] * i1, hi, lo);
        *(unsigned*)(chi + (row0 + 8) * (NHQ * HD) + col) = hi;
        *(unsigned*)(clo + (row0 + 8) * (NHQ * HD) + col) = lo;
    }
}

// ---------------- RMSNorm + RoPE + split + transpose ----------------
__device__ __forceinline__ float blockSum128(float v) {
    #pragma unroll
    for (int o = 16; o > 0; o >>= 1) v += __shfl_xor_sync(0xffffffffu, v, o);
    __shared__ float s[4];
    if ((threadIdx.x & 31) == 0) s[threadIdx.x >> 5] = v;
    __syncthreads();
    float r = s[0] + s[1] + s[2] + s[3];
    __syncthreads();
    return r;
}

__global__ __launch_bounds__(HD) void normrope_kernel(
    const float* __restrict__ qraw, const float* __restrict__ kraw,
    const float* __restrict__ vraw,
    const float* __restrict__ qw, const float* __restrict__ kw,
    const int* __restrict__ pos,
    bf16* __restrict__ qhi, bf16* __restrict__ qlo,
    bf16* __restrict__ khi, bf16* __restrict__ klo,
    bf16* __restrict__ vhi, bf16* __restrict__ vlo)
{
    int row = blockIdx.y;
    int hh  = blockIdx.x;
    int t   = threadIdx.x;
    int b   = row / SEQ, s = row - b * SEQ;

    if (hh >= NHQ + NKV) {            // V: split + transpose
        int kvh = hh - NHQ - NKV;
        float x = vraw[(size_t)row * (NKV * HD) + kvh * HD + t];
        size_t o = (((size_t)(b * NKV + kvh)) * SEQ + s) * HD + t;
        bf16 hv = __float2bfloat16(x);
        vhi[o] = hv;
        vlo[o] = __float2bfloat16(x - __bfloat162float(hv));
        return;
    }

    float x; const float* w;
    bf16 *dhi, *dlo;
    bool isq = (hh < NHQ);
    if (isq) {
        x = qraw[(size_t)row * (NHQ * HD) + hh * HD + t];
        w = qw;
        size_t o = (((size_t)(b * NHQ + hh)) * SEQ + s) * HD + t;
        dhi = qhi + o; dlo = qlo + o;
    } else {
        int kvh = hh - NHQ;
        x = kraw[(size_t)row * (NKV * HD) + kvh * HD + t];
        w = kw;
        size_t o = (((size_t)(b * NKV + kvh)) * SEQ + s) * HD + t;
        dhi = khi + o; dlo = klo + o;
    }

    float ms = blockSum128(x * x) * (1.0f / HD);
    float nv = w[t] * (x * rsqrtf(ms + EPSV));

    __shared__ float sh[HD];
    sh[t] = nv;
    __syncthreads();

    int j = t & 63;
    double invf = exp(-(2.0 * j / (double)HD) * log(1.0e6));
    double ang  = (double)pos[s] * invf;
    float c  = (float)cos(ang);
    float sn = (float)sin(ang);
    float partner = (t < 64) ? -sh[t + 64] : sh[t - 64];
    float val = nv * c + partner * sn;
    if (isq) val *= QSCALE;

    bf16 hv = __float2bfloat16(val);
    *dhi = hv;
    *dlo = __float2bfloat16(val - __bfloat162float(hv));
}

// ---------------- launch ----------------
template <typename T>
static T* symaddr(const void* sym) {
    void* p = nullptr;
    cudaGetSymbolAddress(&p, sym);
    return (T*)p;
}

extern "C" void kernel_launch(void* const* d_in, const int* in_sizes, int n_in,
                              void* d_out, int out_size)
{
    const float* X   = (const float*)d_in[0];
    const int*   pos = (const int*)d_in[1];
    const float* Wq  = (const float*)d_in[2];
    const float* Wk  = (const float*)d_in[3];
    const float* Wv  = (const float*)d_in[4];
    const float* Wo  = (const float*)d_in[5];
    const float* qw  = (const float*)d_in[6];
    const float* kw  = (const float*)d_in[7];
    float* out = (float*)d_out;

    float* qraw = symaddr<float>(g_qraw);
    float* kraw = symaddr<float>(g_kraw);
    float* vraw = symaddr<float>(g_vraw);
    bf16* xhi = symaddr<bf16>(g_xhi);   bf16* xlo = symaddr<bf16>(g_xlo);
    bf16* wqhi = symaddr<bf16>(g_wqhi); bf16* wqlo = symaddr<bf16>(g_wqlo);
    bf16* wkhi = symaddr<bf16>(g_wkhi); bf16* wklo = symaddr<bf16>(g_wklo);
    bf16* wvhi = symaddr<bf16>(g_wvhi); bf16* wvlo = symaddr<bf16>(g_wvlo);
    bf16* wohi = symaddr<bf16>(g_wohi); bf16* wolo = symaddr<bf16>(g_wolo);
    bf16* qhi = symaddr<bf16>(g_qhi);   bf16* qlo = symaddr<bf16>(g_qlo);
    bf16* khi = symaddr<bf16>(g_khi);   bf16* klo = symaddr<bf16>(g_klo);
    bf16* vhi = symaddr<bf16>(g_vhi);   bf16* vlo = symaddr<bf16>(g_vlo);
    bf16* chi = symaddr<bf16>(g_chi);   bf16* clo = symaddr<bf16>(g_clo);

    static int attr_done = 0;
    if (!attr_done) {
        cudaFuncSetAttribute(gemm_split, cudaFuncAttributeMaxDynamicSharedMemorySize, 65536);
        cudaFuncSetAttribute(flash_kernel, cudaFuncAttributeMaxDynamicSharedMemorySize, 196608);
        attr_done = 1;
    }

    // 0) splits
    split_kernel<<<1024, 256>>>(X, xhi, xlo, ROWS * HID);
    split_kernel<<<1024, 256>>>(Wq, wqhi, wqlo, HID * NHQ * HD);
    split_kernel<<<1024, 256>>>(Wk, wkhi, wklo, HID * NKV * HD);
    split_kernel<<<1024, 256>>>(Wv, wvhi, wvlo, HID * NKV * HD);
    split_kernel<<<1024, 256>>>(Wo, wohi, wolo, NHQ * HD * HID);

    // 1) QKV projections
    gemm_split<<<dim3((NHQ * HD) / GBN, ROWS / GBM), 256, 65536>>>(
        xhi, xlo, wqhi, wqlo, qraw, ROWS, NHQ * HD, HID);
    gemm_split<<<dim3((NKV * HD) / GBN, ROWS / GBM), 256, 65536>>>(
        xhi, xlo, wkhi, wklo, kraw, ROWS, NKV * HD, HID);
    gemm_split<<<dim3((NKV * HD) / GBN, ROWS / GBM), 256, 65536>>>(
        xhi, xlo, wvhi, wvlo, vraw, ROWS, NKV * HD, HID);

    // 2) RMSNorm + RoPE + split
    normrope_kernel<<<dim3(NHQ + 2 * NKV, ROWS), HD>>>(
        qraw, kraw, vraw, qw, kw, pos, qhi, qlo, khi, klo, vhi, vlo);

    // 3) fused flash attention -> ctx hi/lo
    flash_kernel<<<dim3(SEQ / 128, BATCH * NHQ), 256, 196608>>>(
        qhi, qlo, khi, klo, vhi, vlo, chi, clo);

    // 4) out = ctx @ Wo
    gemm_split<<<dim3(HID / GBN, ROWS / GBM), 256, 65536>>>(
        chi, clo, wohi, wolo, out, ROWS, HID, NHQ * HD);
}